// round 1
// baseline (speedup 1.0000x reference)
#include <cuda_runtime.h>
#include <math_constants.h>

#define BB 4
#define TT 2048
#define CC 576
#define HH 12
#define DD 48
#define MM (BB*TT)       /* 8192 */
#define NQKV (3*CC)      /* 1728 */

// Scratch (device globals: allocation-free)
__device__ float g_q[BB*HH*TT*DD];
__device__ float g_k[BB*HH*TT*DD];
__device__ float g_v[BB*HH*TT*DD];
__device__ float g_y[BB*TT*CC];

// ---------------------------------------------------------------------------
// Tiled GEMM: out[m][n] = sum_k A[m][k] * W[n][k]
// BM=BN=64, BK=16, 256 threads, 4x4 microtile per thread.
// scatter!=0 -> qkv epilogue: scatter into g_q/g_k/g_v with [B,H,T,D] layout.
// scatter==0 -> plain row-major write to out (leading dim Ndim).
// ---------------------------------------------------------------------------
__global__ void gemm64(const float* __restrict__ A, const float* __restrict__ W,
                       float* __restrict__ out, int Kdim, int Ndim, int scatter)
{
    __shared__ float As[16 * 68];
    __shared__ float Ws[16 * 68];

    const int tid = threadIdx.x;
    const int tm  = tid >> 4;        // 0..15
    const int tn  = tid & 15;        // 0..15
    const int m0  = blockIdx.y * 64;
    const int n0  = blockIdx.x * 64;
    const int lr  = tid >> 2;        // 0..63 (load row)
    const int lc  = tid & 3;         // 0..3  (k-chunk of 4)

    float acc[4][4];
#pragma unroll
    for (int i = 0; i < 4; i++)
#pragma unroll
        for (int j = 0; j < 4; j++) acc[i][j] = 0.f;

    for (int k0 = 0; k0 < Kdim; k0 += 16) {
        float4 a = *(const float4*)(A + (size_t)(m0 + lr) * Kdim + k0 + lc * 4);
        float4 w = *(const float4*)(W + (size_t)(n0 + lr) * Kdim + k0 + lc * 4);
        __syncthreads();
        As[(lc * 4 + 0) * 68 + lr] = a.x;
        As[(lc * 4 + 1) * 68 + lr] = a.y;
        As[(lc * 4 + 2) * 68 + lr] = a.z;
        As[(lc * 4 + 3) * 68 + lr] = a.w;
        Ws[(lc * 4 + 0) * 68 + lr] = w.x;
        Ws[(lc * 4 + 1) * 68 + lr] = w.y;
        Ws[(lc * 4 + 2) * 68 + lr] = w.z;
        Ws[(lc * 4 + 3) * 68 + lr] = w.w;
        __syncthreads();
#pragma unroll
        for (int kk = 0; kk < 16; kk++) {
            float4 ra = *(const float4*)&As[kk * 68 + tm * 4];
            float4 rb = *(const float4*)&Ws[kk * 68 + tn * 4];
            float av[4] = {ra.x, ra.y, ra.z, ra.w};
            float bv[4] = {rb.x, rb.y, rb.z, rb.w};
#pragma unroll
            for (int i = 0; i < 4; i++)
#pragma unroll
                for (int j = 0; j < 4; j++) acc[i][j] += av[i] * bv[j];
        }
    }

    if (scatter) {
#pragma unroll
        for (int i = 0; i < 4; i++) {
            int m = m0 + tm * 4 + i;
            int b = m / TT, t = m % TT;
#pragma unroll
            for (int j = 0; j < 4; j++) {
                int n = n0 + tn * 4 + j;
                int which = n / CC;
                int c = n % CC;
                int h = c / DD, d = c % DD;
                float* dst = (which == 0) ? g_q : (which == 1) ? g_k : g_v;
                dst[(((size_t)b * HH + h) * TT + t) * DD + d] = acc[i][j];
            }
        }
    } else {
#pragma unroll
        for (int i = 0; i < 4; i++) {
            int m = m0 + tm * 4 + i;
#pragma unroll
            for (int j = 0; j < 4; j++) {
                int n = n0 + tn * 4 + j;
                out[(size_t)m * Ndim + n] = acc[i][j];
            }
        }
    }
}

// ---------------------------------------------------------------------------
// Flash attention (causal; ALiBi bias is identically zero on the causal
// region, so it is dropped). BR=BC=64, 256 threads, 4 threads per query row.
// Thread (r, qd) handles cols c = qd + 4*cc, cc=0..15 (interleaved ->
// conflict-free LDS.128 on K/V tiles padded to 13 float4 per row).
// ---------------------------------------------------------------------------
__global__ void attn_kernel(float* __restrict__ ypre)
{
    const int rb  = blockIdx.x;       // row block, 0..31
    const int h   = blockIdx.y;
    const int b   = blockIdx.z;
    const int tid = threadIdx.x;      // 256
    const int r   = tid >> 2;         // 0..63
    const int qd  = tid & 3;          // 0..3
    const int t0  = rb * 64;
    const size_t bh = ((size_t)b * HH + h) * TT;

    __shared__ float4 Ks[64 * 13];
    __shared__ float4 Vs[64 * 13];

    // Q row in registers
    float4 q[12];
    const float4* Qp = (const float4*)(g_q + (bh + t0 + r) * DD);
#pragma unroll
    for (int i = 0; i < 12; i++) q[i] = Qp[i];

    float o[48];
#pragma unroll
    for (int i = 0; i < 48; i++) o[i] = 0.f;
    float mrow = -1e30f, lsum = 0.f;
    const float scale = 0.14433756729740643f;  // 1/sqrt(48)

    for (int jb = 0; jb <= rb; jb++) {
        const float* Kp = g_k + (bh + (size_t)jb * 64) * DD;
        const float* Vp = g_v + (bh + (size_t)jb * 64) * DD;
        __syncthreads();
#pragma unroll
        for (int it = 0; it < 3; it++) {
            int idx = tid + it * 256;
            int cj = idx / 12, c4 = idx % 12;
            Ks[cj * 13 + c4] = ((const float4*)(Kp + cj * 48))[c4];
            Vs[cj * 13 + c4] = ((const float4*)(Vp + cj * 48))[c4];
        }
        __syncthreads();

        float s[16];
#pragma unroll
        for (int cc = 0; cc < 16; cc++) {
            int c = qd + cc * 4;
            float a = 0.f;
#pragma unroll
            for (int d4 = 0; d4 < 12; d4++) {
                float4 kv = Ks[c * 13 + d4];
                a += q[d4].x * kv.x;
                a += q[d4].y * kv.y;
                a += q[d4].z * kv.z;
                a += q[d4].w * kv.w;
            }
            s[cc] = a * scale;
        }
        if (jb == rb) {
#pragma unroll
            for (int cc = 0; cc < 16; cc++) {
                int c = qd + cc * 4;
                if (c > r) s[cc] = -1e30f;
            }
        }
        float mj = -1e30f;
#pragma unroll
        for (int cc = 0; cc < 16; cc++) mj = fmaxf(mj, s[cc]);
        mj = fmaxf(mj, __shfl_xor_sync(0xffffffffu, mj, 1));
        mj = fmaxf(mj, __shfl_xor_sync(0xffffffffu, mj, 2));
        float mnew = fmaxf(mrow, mj);
        float corr = __expf(mrow - mnew);
        float p[16];
        float ps = 0.f;
#pragma unroll
        for (int cc = 0; cc < 16; cc++) {
            p[cc] = __expf(s[cc] - mnew);
            ps += p[cc];
        }
        lsum = lsum * corr + ps;
        mrow = mnew;
#pragma unroll
        for (int i = 0; i < 48; i++) o[i] *= corr;
#pragma unroll
        for (int cc = 0; cc < 16; cc++) {
            int c = qd + cc * 4;
            float pc = p[cc];
#pragma unroll
            for (int d4 = 0; d4 < 12; d4++) {
                float4 vv = Vs[c * 13 + d4];
                o[d4 * 4 + 0] += pc * vv.x;
                o[d4 * 4 + 1] += pc * vv.y;
                o[d4 * 4 + 2] += pc * vv.z;
                o[d4 * 4 + 3] += pc * vv.w;
            }
        }
    }

    // combine the 4 lanes of each row
    lsum += __shfl_xor_sync(0xffffffffu, lsum, 1);
    lsum += __shfl_xor_sync(0xffffffffu, lsum, 2);
#pragma unroll
    for (int i = 0; i < 48; i++) {
        o[i] += __shfl_xor_sync(0xffffffffu, o[i], 1);
        o[i] += __shfl_xor_sync(0xffffffffu, o[i], 2);
    }
    if (qd == 0) {
        float inv = 1.f / lsum;
        float* dst = ypre + ((size_t)b * TT + t0 + r) * CC + h * DD;
#pragma unroll
        for (int i = 0; i < 12; i++) {
            float4 v4 = make_float4(o[i * 4 + 0] * inv, o[i * 4 + 1] * inv,
                                    o[i * 4 + 2] * inv, o[i * 4 + 3] * inv);
            ((float4*)dst)[i] = v4;
        }
    }
}

extern "C" void kernel_launch(void* const* d_in, const int* in_sizes, int n_in,
                              void* d_out, int out_size)
{
    (void)in_sizes; (void)n_in; (void)out_size;
    const float* x      = (const float*)d_in[0];
    const float* w_qkv  = (const float*)d_in[1];
    const float* w_proj = (const float*)d_in[2];
    float* out = (float*)d_out;

    float* yptr = nullptr;
    cudaGetSymbolAddress((void**)&yptr, g_y);

    // 1) qkv GEMM + scatter into q/k/v [B,H,T,D]
    {
        dim3 grid(NQKV / 64, MM / 64);
        gemm64<<<grid, 256>>>(x, w_qkv, nullptr, CC, NQKV, 1);
    }
    // 2) causal flash attention -> g_y [B,T,C]
    {
        dim3 grid(TT / 64, HH, BB);
        attn_kernel<<<grid, 256>>>(yptr);
    }
    // 3) output projection
    {
        dim3 grid(CC / 64, MM / 64);
        gemm64<<<grid, 256>>>(yptr, w_proj, out, CC, CC, 0);
    }
}

// round 3
// speedup vs baseline: 3.7078x; 3.7078x over previous
#include <cuda_runtime.h>

#define BB 4
#define TT 2048
#define CC 576
#define HH 12
#define DD 48
#define MM (BB*TT)       /* 8192 */
#define NQKV (3*CC)      /* 1728 */

// Scratch (device globals: allocation-free). q/k/v stored pre-rounded to tf32
// (q additionally pre-scaled by 1/sqrt(48)).
__device__ float g_q[BB*HH*TT*DD];
__device__ float g_k[BB*HH*TT*DD];
__device__ float g_v[BB*HH*TT*DD];
__device__ float g_y[BB*TT*CC];

// ---------------------------------------------------------------------------
// helpers
// ---------------------------------------------------------------------------
__device__ __forceinline__ unsigned f2tf(float x) {
    unsigned r;
    asm("cvt.rna.tf32.f32 %0, %1;" : "=r"(r) : "f"(x));
    return r;
}

__device__ __forceinline__ void mma_tf32(float c[4],
                                         unsigned a0, unsigned a1, unsigned a2, unsigned a3,
                                         unsigned b0, unsigned b1) {
    asm volatile(
        "mma.sync.aligned.m16n8k8.row.col.f32.tf32.tf32.f32 "
        "{%0,%1,%2,%3}, {%4,%5,%6,%7}, {%8,%9}, {%0,%1,%2,%3};"
        : "+f"(c[0]), "+f"(c[1]), "+f"(c[2]), "+f"(c[3])
        : "r"(a0), "r"(a1), "r"(a2), "r"(a3), "r"(b0), "r"(b1));
}

// FMA-pipe exp (no MUFU): exp(x) for x <= 0, rel err ~3e-6.
__device__ __forceinline__ float fexp(float x) {
    x = fmaxf(x, -80.f);
    float u = x * 1.4426950408889634f;
    float t = u + 12582912.f;                       // round-to-nearest via magic
    int   i = __float_as_int(t) - 0x4B400000;
    float f = u - (t - 12582912.f);                 // f in [-0.5, 0.5]
    float p = fmaf(f, 0.0013333558f, 0.0096181291f);
    p = fmaf(f, p, 0.055504109f);
    p = fmaf(f, p, 0.24022651f);
    p = fmaf(f, p, 0.69314718f);
    p = fmaf(f, p, 1.0f);
    return p * __int_as_float((i + 127) << 23);
}

// ---------------------------------------------------------------------------
// TF32 tensor-core GEMM: out[m][n] = sum_k A[m][k]*W[n][k], K = 576 fixed.
// Block 128x64, 256 threads (8 warps as 4x2), warp tile 32x32 (2x4 m16n8k8).
// scatter!=0: qkv epilogue -> g_q (pre-scaled) / g_k / g_v, all tf32-rounded.
// ---------------------------------------------------------------------------
#define SA 36
#define SB 36
__global__ void gemm_tc(const float* __restrict__ A, const float* __restrict__ W,
                        float* __restrict__ out, int Ndim, int scatter)
{
    __shared__ float As[128 * SA];
    __shared__ float Bs[64 * SB];

    const int tid  = threadIdx.x;
    const int wid  = tid >> 5, lane = tid & 31;
    const int wm   = wid >> 1, wn = wid & 1;
    const int g    = lane >> 2, c = lane & 3;
    const int m0   = blockIdx.y * 128;
    const int n0   = blockIdx.x * 64;

    const int arow = tid >> 1, akq = (tid & 1) * 16;
    const int brow = tid >> 2, bkq = (tid & 3) * 8;

    float acc[2][4][4];
#pragma unroll
    for (int i = 0; i < 2; i++)
#pragma unroll
        for (int j = 0; j < 4; j++)
#pragma unroll
            for (int e = 0; e < 4; e++) acc[i][j][e] = 0.f;

    for (int k0 = 0; k0 < 576; k0 += 32) {
        float4 av[4], wv[2];
        const float4* Ap = (const float4*)(A + (size_t)(m0 + arow) * 576 + k0 + akq);
        const float4* Wp = (const float4*)(W + (size_t)(n0 + brow) * 576 + k0 + bkq);
#pragma unroll
        for (int i = 0; i < 4; i++) av[i] = Ap[i];
#pragma unroll
        for (int i = 0; i < 2; i++) wv[i] = Wp[i];
        __syncthreads();
#pragma unroll
        for (int i = 0; i < 4; i++) {
            float4 v;
            v.x = __uint_as_float(f2tf(av[i].x));
            v.y = __uint_as_float(f2tf(av[i].y));
            v.z = __uint_as_float(f2tf(av[i].z));
            v.w = __uint_as_float(f2tf(av[i].w));
            *(float4*)&As[arow * SA + akq + 4 * i] = v;
        }
#pragma unroll
        for (int i = 0; i < 2; i++) {
            float4 v;
            v.x = __uint_as_float(f2tf(wv[i].x));
            v.y = __uint_as_float(f2tf(wv[i].y));
            v.z = __uint_as_float(f2tf(wv[i].z));
            v.w = __uint_as_float(f2tf(wv[i].w));
            *(float4*)&Bs[brow * SB + bkq + 4 * i] = v;
        }
        __syncthreads();

#pragma unroll
        for (int kk = 0; kk < 4; kk++) {
            const int kb = kk * 8;
            unsigned a[2][4], bfr[4][2];
#pragma unroll
            for (int i = 0; i < 2; i++) {
                const int mr = wm * 32 + i * 16;
                a[i][0] = __float_as_uint(As[(mr + g) * SA + kb + c]);
                a[i][1] = __float_as_uint(As[(mr + g + 8) * SA + kb + c]);
                a[i][2] = __float_as_uint(As[(mr + g) * SA + kb + c + 4]);
                a[i][3] = __float_as_uint(As[(mr + g + 8) * SA + kb + c + 4]);
            }
#pragma unroll
            for (int j = 0; j < 4; j++) {
                const int nc = wn * 32 + j * 8;
                bfr[j][0] = __float_as_uint(Bs[(nc + g) * SB + kb + c]);
                bfr[j][1] = __float_as_uint(Bs[(nc + g) * SB + kb + c + 4]);
            }
#pragma unroll
            for (int i = 0; i < 2; i++)
#pragma unroll
                for (int j = 0; j < 4; j++)
                    mma_tf32(acc[i][j], a[i][0], a[i][1], a[i][2], a[i][3],
                             bfr[j][0], bfr[j][1]);
        }
    }

    const float qscale = 0.14433756729740643f;  // 1/sqrt(48)
#pragma unroll
    for (int i = 0; i < 2; i++) {
#pragma unroll
        for (int j = 0; j < 4; j++) {
            const int col = n0 + wn * 32 + j * 8 + 2 * c;
#pragma unroll
            for (int half = 0; half < 2; half++) {
                const int m = m0 + wm * 32 + i * 16 + g + half * 8;
                float v0 = acc[i][j][half * 2 + 0];
                float v1 = acc[i][j][half * 2 + 1];
                if (scatter) {
                    const int b = m >> 11, t = m & 2047;
                    const int which = col / CC;
                    const int cc = col - which * CC;
                    const int h = cc / DD, d = cc - h * DD;
                    float* dst = (which == 0) ? g_q : (which == 1) ? g_k : g_v;
                    if (which == 0) { v0 *= qscale; v1 *= qscale; }
                    float2 st;
                    st.x = __uint_as_float(f2tf(v0));
                    st.y = __uint_as_float(f2tf(v1));
                    *(float2*)&dst[(((size_t)b * HH + h) * TT + t) * DD + d] = st;
                } else {
                    float2 st; st.x = v0; st.y = v1;
                    *(float2*)&out[(size_t)m * Ndim + col] = st;
                }
            }
        }
    }
}

// ---------------------------------------------------------------------------
// Flash attention, tf32 tensor cores. BR=BC=64, 128 threads = 4 warps,
// warp w owns rows w*16..w*16+15 (one m16 fragment row-set).
// S = Q K^T via mma (Q a-frags in regs, K from smem). Softmax with FMA-exp.
// P staged through smem (tf32) to re-fragment for P·V mma.
// K/V smem rows hold 48 floats: strides MUST be >= 48 (52/56; also chosen so
// stride mod 32 banks = 20/24 -> conflict-free fragment reads).
// ---------------------------------------------------------------------------
#define SK 52
#define SV 56
#define SP 68
__global__ void attn_tc(float* __restrict__ ypre)
{
    __shared__ float Ks[64 * SK];
    __shared__ float Vs[64 * SV];
    __shared__ float Ps[64 * SP];

    const int rb = blockIdx.x, h = blockIdx.y, b = blockIdx.z;
    const int tid = threadIdx.x, wid = tid >> 5, lane = tid & 31;
    const int g = lane >> 2, c = lane & 3;
    const int t0 = rb * 64;
    const size_t bh = ((size_t)b * HH + h) * TT;

    // Q a-fragments (values pre-scaled & tf32-rounded by the qkv epilogue)
    const float* Qb = g_q + (bh + t0 + wid * 16) * DD;
    unsigned qa[6][4];
#pragma unroll
    for (int k = 0; k < 6; k++) {
        qa[k][0] = __float_as_uint(Qb[(g) * DD + k * 8 + c]);
        qa[k][1] = __float_as_uint(Qb[(g + 8) * DD + k * 8 + c]);
        qa[k][2] = __float_as_uint(Qb[(g) * DD + k * 8 + c + 4]);
        qa[k][3] = __float_as_uint(Qb[(g + 8) * DD + k * 8 + c + 4]);
    }

    float o[6][4];
#pragma unroll
    for (int nf = 0; nf < 6; nf++)
#pragma unroll
        for (int e = 0; e < 4; e++) o[nf][e] = 0.f;
    float ma = -1e30f, mb = -1e30f, la = 0.f, lb = 0.f;

    const int ldrow = tid >> 1, ldd = (tid & 1) * 24;

    for (int jb = 0; jb <= rb; jb++) {
        const float* Kp = g_k + (bh + (size_t)jb * 64) * DD;
        const float* Vp = g_v + (bh + (size_t)jb * 64) * DD;
        __syncthreads();
        {
            const float4* kr = (const float4*)(Kp + ldrow * DD + ldd);
            const float4* vr = (const float4*)(Vp + ldrow * DD + ldd);
            float4 kk[6], vv[6];
#pragma unroll
            for (int i = 0; i < 6; i++) { kk[i] = kr[i]; vv[i] = vr[i]; }
#pragma unroll
            for (int i = 0; i < 6; i++) {
                *(float4*)&Ks[ldrow * SK + ldd + 4 * i] = kk[i];
                *(float4*)&Vs[ldrow * SV + ldd + 4 * i] = vv[i];
            }
        }
        __syncthreads();

        // S = Q K^T  (8 n-frags over the 64 keys)
        float s[8][4];
#pragma unroll
        for (int f = 0; f < 8; f++) {
#pragma unroll
            for (int e = 0; e < 4; e++) s[f][e] = 0.f;
#pragma unroll
            for (int k = 0; k < 6; k++) {
                unsigned b0 = __float_as_uint(Ks[(f * 8 + g) * SK + k * 8 + c]);
                unsigned b1 = __float_as_uint(Ks[(f * 8 + g) * SK + k * 8 + c + 4]);
                mma_tf32(s[f], qa[k][0], qa[k][1], qa[k][2], qa[k][3], b0, b1);
            }
        }

        if (jb == rb) {
            const int ra = wid * 16 + g;       // in-block row (c0,c1)
            const int rbx = ra + 8;            // in-block row (c2,c3)
#pragma unroll
            for (int f = 0; f < 8; f++) {
                const int col = f * 8 + 2 * c;
                if (col > ra)      s[f][0] = -1e30f;
                if (col + 1 > ra)  s[f][1] = -1e30f;
                if (col > rbx)     s[f][2] = -1e30f;
                if (col + 1 > rbx) s[f][3] = -1e30f;
            }
        }

        // online softmax (FMA-pipe exp, no MUFU)
        float mja = -1e30f, mjb = -1e30f;
#pragma unroll
        for (int f = 0; f < 8; f++) {
            mja = fmaxf(mja, fmaxf(s[f][0], s[f][1]));
            mjb = fmaxf(mjb, fmaxf(s[f][2], s[f][3]));
        }
        mja = fmaxf(mja, __shfl_xor_sync(0xffffffffu, mja, 1));
        mja = fmaxf(mja, __shfl_xor_sync(0xffffffffu, mja, 2));
        mjb = fmaxf(mjb, __shfl_xor_sync(0xffffffffu, mjb, 1));
        mjb = fmaxf(mjb, __shfl_xor_sync(0xffffffffu, mjb, 2));
        const float mna = fmaxf(ma, mja), mnb = fmaxf(mb, mjb);
        const float ca = fexp(ma - mna), cb = fexp(mb - mnb);
        float psa = 0.f, psb = 0.f;
#pragma unroll
        for (int f = 0; f < 8; f++) {
            s[f][0] = fexp(s[f][0] - mna); psa += s[f][0];
            s[f][1] = fexp(s[f][1] - mna); psa += s[f][1];
            s[f][2] = fexp(s[f][2] - mnb); psb += s[f][2];
            s[f][3] = fexp(s[f][3] - mnb); psb += s[f][3];
        }
        ma = mna; mb = mnb;
        la = la * ca + psa;
        lb = lb * cb + psb;
#pragma unroll
        for (int nf = 0; nf < 6; nf++) {
            o[nf][0] *= ca; o[nf][1] *= ca;
            o[nf][2] *= cb; o[nf][3] *= cb;
        }

        // stage P (tf32) through per-warp-private smem slab
        {
            const int pra = wid * 16 + g;
#pragma unroll
            for (int f = 0; f < 8; f++) {
                const int col = f * 8 + 2 * c;
                Ps[pra * SP + col]           = __uint_as_float(f2tf(s[f][0]));
                Ps[pra * SP + col + 1]       = __uint_as_float(f2tf(s[f][1]));
                Ps[(pra + 8) * SP + col]     = __uint_as_float(f2tf(s[f][2]));
                Ps[(pra + 8) * SP + col + 1] = __uint_as_float(f2tf(s[f][3]));
            }
        }
        __syncwarp();

        // O += P V  (8 k-steps over keys, 6 n-frags over d)
        const int prow = wid * 16;
#pragma unroll
        for (int k = 0; k < 8; k++) {
            unsigned pa0 = __float_as_uint(Ps[(prow + g) * SP + k * 8 + c]);
            unsigned pa1 = __float_as_uint(Ps[(prow + g + 8) * SP + k * 8 + c]);
            unsigned pa2 = __float_as_uint(Ps[(prow + g) * SP + k * 8 + c + 4]);
            unsigned pa3 = __float_as_uint(Ps[(prow + g + 8) * SP + k * 8 + c + 4]);
#pragma unroll
            for (int nf = 0; nf < 6; nf++) {
                unsigned b0 = __float_as_uint(Vs[(k * 8 + c) * SV + nf * 8 + g]);
                unsigned b1 = __float_as_uint(Vs[(k * 8 + c + 4) * SV + nf * 8 + g]);
                mma_tf32(o[nf], pa0, pa1, pa2, pa3, b0, b1);
            }
        }
    }

    // finalize
    la += __shfl_xor_sync(0xffffffffu, la, 1);
    la += __shfl_xor_sync(0xffffffffu, la, 2);
    lb += __shfl_xor_sync(0xffffffffu, lb, 1);
    lb += __shfl_xor_sync(0xffffffffu, lb, 2);
    const float ia = 1.f / la, ib = 1.f / lb;
    const int ra = t0 + wid * 16 + g;
    float* ya = ypre + ((size_t)b * TT + ra) * CC + h * DD;
    float* yb = ypre + ((size_t)b * TT + ra + 8) * CC + h * DD;
#pragma unroll
    for (int nf = 0; nf < 6; nf++) {
        const int d = nf * 8 + 2 * c;
        float2 sa; sa.x = o[nf][0] * ia; sa.y = o[nf][1] * ia;
        float2 sb; sb.x = o[nf][2] * ib; sb.y = o[nf][3] * ib;
        *(float2*)&ya[d] = sa;
        *(float2*)&yb[d] = sb;
    }
}

extern "C" void kernel_launch(void* const* d_in, const int* in_sizes, int n_in,
                              void* d_out, int out_size)
{
    (void)in_sizes; (void)n_in; (void)out_size;
    const float* x      = (const float*)d_in[0];
    const float* w_qkv  = (const float*)d_in[1];
    const float* w_proj = (const float*)d_in[2];
    float* out = (float*)d_out;

    float* yptr = nullptr;
    cudaGetSymbolAddress((void**)&yptr, g_y);

    // 1) qkv GEMM (tf32 TC) + scatter into q/k/v [B,H,T,D], pre-scaled/rounded
    {
        dim3 grid(NQKV / 64, MM / 128);
        gemm_tc<<<grid, 256>>>(x, w_qkv, nullptr, NQKV, 1);
    }
    // 2) causal flash attention (tf32 TC) -> g_y [B,T,C]
    {
        dim3 grid(TT / 64, HH, BB);
        attn_tc<<<grid, 128>>>(yptr);
    }
    // 3) output projection (tf32 TC)
    {
        dim3 grid(CC / 64, MM / 128);
        gemm_tc<<<grid, 256>>>(yptr, w_proj, out, CC, 0);
    }
}